// round 16
// baseline (speedup 1.0000x reference)
#include <cuda_runtime.h>
#include <cstdint>

// 9 global moment accumulators + ticket. Zero at module load; the last block
// resets them each launch -> clean state for every graph replay. Integer
// atomics on exact integer-valued data -> deterministic.
__device__ unsigned int g_counts[9];
__device__ unsigned int g_ticket;

// Moment accumulation (proven R12-R14): labels are exact small ints in fp32,
// so all sums stay exact (< 2^24 per block). FMA-pipe heavy; issue ~37%.
#define LANE(x, y) do {                                   \
    float tx = (x) * (x);                                 \
    sa1 += (x);  sa2 += tx;  sa3 = fmaf(tx, (x), sa3);    \
    float ty = (y) * (y);                                 \
    sb1 += (y);  sb2 += ty;  sb3 = fmaf(ty, (y), sb3);    \
    float d  = ((x) == (y)) ? (x) : 0.0f;                 \
    float td = d * d;                                     \
    si1 += d;    si2 += td;  si3 = fmaf(td, d, si3);      \
} while (0)

__global__ void __launch_bounds__(256, 8) dice_fused_kernel(
    const float4* __restrict__ a, const float4* __restrict__ b,
    int n_vec, float* __restrict__ out)
{
    float sa1 = 0.f, sa2 = 0.f, sa3 = 0.f;
    float sb1 = 0.f, sb2 = 0.f, sb3 = 0.f;
    float si1 = 0.f, si2 = 0.f, si3 = 0.f;

    const int stride = gridDim.x * blockDim.x;
    int idx = blockIdx.x * blockDim.x + threadIdx.x;

    // unroll 16: measured optimum (8 -> 155.5us, 16 -> 154.9us, 32 -> 158.2us
    // on-kernel; 32 crosses the I$ transition band).
    #pragma unroll 16
    for (; idx < n_vec; idx += stride) {
        float4 va = __ldcs(&a[idx]);
        float4 vb = __ldcs(&b[idx]);
        LANE(va.x, vb.x);
        LANE(va.y, vb.y);
        LANE(va.z, vb.z);
        LANE(va.w, vb.w);
    }

    // warp reduce 9 float moments (exact integers throughout)
    float v[9] = {sa1, sa2, sa3, sb1, sb2, sb3, si1, si2, si3};
    #pragma unroll
    for (int k = 0; k < 9; ++k) {
        #pragma unroll
        for (int off = 16; off > 0; off >>= 1)
            v[k] += __shfl_down_sync(0xFFFFFFFFu, v[k], off);
    }

    // block reduce: warp leaders -> shared, lanes 0..8 finish
    __shared__ float ws[8][9];
    if ((threadIdx.x & 31) == 0) {
        #pragma unroll
        for (int k = 0; k < 9; ++k) ws[threadIdx.x >> 5][k] = v[k];
    }
    __syncthreads();

    if (threadIdx.x < 9) {
        float t = 0.f;
        #pragma unroll
        for (int w = 0; w < 8; ++w) t += ws[w][threadIdx.x];
        atomicAdd(&g_counts[threadIdx.x], (unsigned int)t);  // exact
    }
    __threadfence();
    if (threadIdx.x == 0) {
        unsigned int t = atomicAdd(&g_ticket, 1u);
        if (t == gridDim.x - 1u) {
            __threadfence();
            unsigned int tot[9];
            #pragma unroll
            for (int k = 0; k < 9; ++k) tot[k] = atomicAdd(&g_counts[k], 0u);

            // Recover counts from moments (labels 1,2,3; exact int64 math):
            //   m1 = c1 + 2c2 + 3c3 ; m2 = c1 + 4c2 + 9c3 ; m3 = c1 + 8c2 + 27c3
            long long cnt[9];
            #pragma unroll
            for (int g = 0; g < 3; ++g) {
                long long m1 = (long long)tot[g * 3 + 0];
                long long m2 = (long long)tot[g * 3 + 1];
                long long m3 = (long long)tot[g * 3 + 2];
                long long c3 = (m3 - 3 * m2 + 2 * m1) / 6;
                long long c2 = (m2 - m1 - 6 * c3) / 2;
                long long c1 = m1 - 2 * c2 - 3 * c3;
                cnt[g * 3 + 0] = c1; cnt[g * 3 + 1] = c2; cnt[g * 3 + 2] = c3;
            }

            const float eps = 1.1920928955078125e-07f;  // np.finfo(float32).eps
            float sum = 0.0f;
            #pragma unroll
            for (int l = 0; l < 3; ++l) {
                float inter = (float)cnt[6 + l];
                float bot   = (float)cnt[l] + (float)cnt[3 + l];
                sum += (2.0f * inter) / (bot + eps);
            }
            out[0] = 1.0f - sum * (1.0f / 3.0f);

            // reset: 9 words + ticket
            #pragma unroll
            for (int k = 0; k < 9; ++k) g_counts[k] = 0u;
            __threadfence();
            g_ticket = 0u;
        }
    }
}

extern "C" void kernel_launch(void* const* d_in, const int* in_sizes, int n_in,
                              void* d_out, int out_size)
{
    const float4* a = (const float4*)d_in[0];
    const float4* b = (const float4*)d_in[1];
    float* out = (float*)d_out;

    int n = in_sizes[0];        // 512^3, divisible by 4
    int n_vec = n >> 2;

    const int threads = 256;
    const int blocks  = 152 * 8;   // 1216
    dice_fused_kernel<<<blocks, threads>>>(a, b, n_vec, out);
}

// round 17
// speedup vs baseline: 1.0114x; 1.0114x over previous
#include <cuda_runtime.h>
#include <cstdint>

// 9 global moment accumulators + ticket. Zero at module load; the last block
// resets them each launch -> clean state for every graph replay. Integer
// atomics on exact integer-valued data -> deterministic.
__device__ unsigned int g_counts[9];
__device__ unsigned int g_ticket;

// Moment accumulation (proven R12-R16): labels are exact small ints in fp32,
// so all sums stay exact (< 2^24 per block). FMA-pipe heavy; issue ~37%.
#define LANE(x, y) do {                                   \
    float tx = (x) * (x);                                 \
    sa1 += (x);  sa2 += tx;  sa3 = fmaf(tx, (x), sa3);    \
    float ty = (y) * (y);                                 \
    sb1 += (y);  sb2 += ty;  sb3 = fmaf(ty, (y), sb3);    \
    float d  = ((x) == (y)) ? (x) : 0.0f;                 \
    float td = d * d;                                     \
    si1 += d;    si2 += td;  si3 = fmaf(td, d, si3);      \
} while (0)

__global__ void __launch_bounds__(128, 16) dice_fused_kernel(
    const float4* __restrict__ a, const float4* __restrict__ b,
    int n_vec, float* __restrict__ out)
{
    float sa1 = 0.f, sa2 = 0.f, sa3 = 0.f;
    float sb1 = 0.f, sb2 = 0.f, sb3 = 0.f;
    float si1 = 0.f, si2 = 0.f, si3 = 0.f;

    const int stride = gridDim.x * blockDim.x;
    int idx = blockIdx.x * blockDim.x + threadIdx.x;

    // unroll 16: measured optimum (8 -> 155.5us, 16 -> 154.9us, 32 -> 158.2us
    // on-kernel; 32 crosses the I$ transition band).
    #pragma unroll 16
    for (; idx < n_vec; idx += stride) {
        float4 va = __ldcs(&a[idx]);
        float4 vb = __ldcs(&b[idx]);
        LANE(va.x, vb.x);
        LANE(va.y, vb.y);
        LANE(va.z, vb.z);
        LANE(va.w, vb.w);
    }

    // warp reduce 9 float moments (exact integers throughout)
    float v[9] = {sa1, sa2, sa3, sb1, sb2, sb3, si1, si2, si3};
    #pragma unroll
    for (int k = 0; k < 9; ++k) {
        #pragma unroll
        for (int off = 16; off > 0; off >>= 1)
            v[k] += __shfl_down_sync(0xFFFFFFFFu, v[k], off);
    }

    // block reduce: 4 warp leaders -> shared, lanes 0..8 finish
    __shared__ float ws[4][9];
    if ((threadIdx.x & 31) == 0) {
        #pragma unroll
        for (int k = 0; k < 9; ++k) ws[threadIdx.x >> 5][k] = v[k];
    }
    __syncthreads();

    if (threadIdx.x < 9) {
        float t = 0.f;
        #pragma unroll
        for (int w = 0; w < 4; ++w) t += ws[w][threadIdx.x];
        atomicAdd(&g_counts[threadIdx.x], (unsigned int)t);  // exact
    }
    __threadfence();
    if (threadIdx.x == 0) {
        unsigned int t = atomicAdd(&g_ticket, 1u);
        if (t == gridDim.x - 1u) {
            __threadfence();
            unsigned int tot[9];
            #pragma unroll
            for (int k = 0; k < 9; ++k) tot[k] = atomicAdd(&g_counts[k], 0u);

            // Recover counts from moments (labels 1,2,3; exact int64 math):
            //   m1 = c1 + 2c2 + 3c3 ; m2 = c1 + 4c2 + 9c3 ; m3 = c1 + 8c2 + 27c3
            long long cnt[9];
            #pragma unroll
            for (int g = 0; g < 3; ++g) {
                long long m1 = (long long)tot[g * 3 + 0];
                long long m2 = (long long)tot[g * 3 + 1];
                long long m3 = (long long)tot[g * 3 + 2];
                long long c3 = (m3 - 3 * m2 + 2 * m1) / 6;
                long long c2 = (m2 - m1 - 6 * c3) / 2;
                long long c1 = m1 - 2 * c2 - 3 * c3;
                cnt[g * 3 + 0] = c1; cnt[g * 3 + 1] = c2; cnt[g * 3 + 2] = c3;
            }

            const float eps = 1.1920928955078125e-07f;  // np.finfo(float32).eps
            float sum = 0.0f;
            #pragma unroll
            for (int l = 0; l < 3; ++l) {
                float inter = (float)cnt[6 + l];
                float bot   = (float)cnt[l] + (float)cnt[3 + l];
                sum += (2.0f * inter) / (bot + eps);
            }
            out[0] = 1.0f - sum * (1.0f / 3.0f);

            // reset: 9 words + ticket
            #pragma unroll
            for (int k = 0; k < 9; ++k) g_counts[k] = 0u;
            __threadfence();
            g_ticket = 0u;
        }
    }
}

extern "C" void kernel_launch(void* const* d_in, const int* in_sizes, int n_in,
                              void* d_out, int out_size)
{
    const float4* a = (const float4*)d_in[0];
    const float4* b = (const float4*)d_in[1];
    float* out = (float*)d_out;

    int n = in_sizes[0];        // 512^3, divisible by 4
    int n_vec = n >> 2;

    const int threads = 128;
    const int blocks  = 152 * 16;   // 2432: 16 CTA/SM, same 2048 thr/SM
    dice_fused_kernel<<<blocks, threads>>>(a, b, n_vec, out);
}